// round 10
// baseline (speedup 1.0000x reference)
#include <cuda_runtime.h>
#include <cstdio>

#define UP      4096
#define HALF    2048
#define QUART   1024
#define LOG2UP  12
#define NB      32
#define NA      256
#define SIGL    2048
#define N1      1024
#define THREADS 256
#define OUT_ELEMS (NB * NA * SIGL)   // 16777216 float32 (real part of Wx)

// Forward-FFT results: (32, 4096) complex64 = 1 MB static device scratch.
__device__ float2 g_xh[NB * UP];
__device__ float g_sink[4];

__device__ __forceinline__ float2 cmul(float2 a, float2 b) {
    return make_float2(a.x * b.x - a.y * b.y, a.x * b.y + a.y * b.x);
}

// ---- safe probes (eager-only): all indices within the 64MB hypothesis ----
__global__ void probe_write_out(float* out, unsigned i0, unsigned i1) {
    if (threadIdx.x == 0) { out[i0] = 0.0f; out[i1] = 0.0f; }
}
__global__ void probe_read_buf(const float* p, unsigned i0, unsigned i1, int slot) {
    if (threadIdx.x == 0) g_sink[slot] = p[i0] + p[i1];
}

// In-place radix-2 DIT FFT over shared buf[UP]; quarter twiddle table twq.
template <bool INVERSE>
__device__ void fft_shared(float2* buf, const float2* twq) {
    const int tid = threadIdx.x;
    for (int i = tid; i < UP; i += THREADS) {
        int j = (int)(__brev((unsigned)i) >> (32 - LOG2UP));
        if (j > i) { float2 t = buf[i]; buf[i] = buf[j]; buf[j] = t; }
    }
    __syncthreads();
    for (int len = 2; len <= UP; len <<= 1) {
        const int half = len >> 1;
        const int step = UP / len;
        for (int t = tid; t < HALF; t += THREADS) {
            const int j = t & (half - 1);
            const int i = ((t & ~(half - 1)) << 1) | j;
            const int m = j * step;
            const float2 q = twq[m & (QUART - 1)];
            float2 w = (m & QUART) ? make_float2(-q.y, q.x) : q;
            if (!INVERSE) w.y = -w.y;
            const float2 u = buf[i];
            const float2 v = cmul(buf[i + half], w);
            buf[i]        = make_float2(u.x + v.x, u.y + v.y);
            buf[i + half] = make_float2(u.x - v.x, u.y - v.y);
        }
        __syncthreads();
    }
}

__device__ __forceinline__ void fill_twiddles(float2* twq) {
    for (int k = threadIdx.x; k < QUART; k += THREADS) {
        float s, c;
        sincospif((float)k * (1.0f / HALF), &s, &c);
        twq[k] = make_float2(c, s);
    }
}

// Kernel 1: reflect-pad signal b, forward FFT, store to g_xh[b].
__global__ void cwt_fwd_kernel(const float* __restrict__ x) {
    __shared__ float2 buf[UP];
    __shared__ float2 twq[QUART];
    const int b   = blockIdx.x;
    const int tid = threadIdx.x;
    const unsigned xbase = (unsigned)b * SIGL;

    for (int i = tid; i < UP; i += THREADS) {
        int src;
        if (i < N1)             src = N1 - i;
        else if (i < N1 + SIGL) src = i - N1;
        else                    src = 5118 - i;
        buf[i] = make_float2(x[xbase + (unsigned)src], 0.0f);
    }
    fill_twiddles(twq);
    __syncthreads();

    fft_shared<false>(buf, twq);

    float2* dst = g_xh + (size_t)b * UP;
    for (int i = tid; i < UP; i += THREADS) dst[i] = buf[i];
}

// Kernel 2: block (a,b): Y = Psih[a]*Xh[b]; IFFT; write Re(crop)/UP as float32.
__global__ void cwt_main_kernel(const float* __restrict__ psih,
                                float* __restrict__ out, unsigned o_lim) {
    __shared__ float2 buf[UP];
    __shared__ float2 twq[QUART];
    const int a   = blockIdx.x;
    const int b   = blockIdx.y;
    const int tid = threadIdx.x;

    const unsigned pbase = (unsigned)a * UP;
    const float2* X = g_xh + (size_t)b * UP;
    for (int i = tid; i < UP; i += THREADS) {
        const float p = psih[pbase + (unsigned)i];
        const float2 xv = X[i];
        buf[i] = make_float2(p * xv.x, p * xv.y);
    }
    fill_twiddles(twq);
    __syncthreads();

    fft_shared<true>(buf, twq);

    const float inv = 1.0f / (float)UP;
    const unsigned obase = ((unsigned)b * NA + (unsigned)a) * SIGL;
    for (int n = tid; n < SIGL; n += THREADS) {
        const unsigned oi = obase + (unsigned)n;
        if (oi < o_lim) out[oi] = buf[N1 + n].x * inv;   // REAL PART ONLY
    }
}

extern "C" void kernel_launch(void* const* d_in, const int* in_sizes, int n_in,
                              void* d_out, int out_size) {
    cudaStreamCaptureStatus cst = cudaStreamCaptureStatusNone;
    cudaStreamIsCapturing(0, &cst);
    const bool quiet = (cst != cudaStreamCaptureStatusNone);

    // Order-robust dispatch (Psih 16x larger than x).
    int xi = 0, pi = 0;
    if (n_in >= 2) {
        if (in_sizes[0] >= in_sizes[1]) { pi = 0; xi = 1; }
        else                            { xi = 0; pi = 1; }
    }
    const float* x    = (const float*)d_in[xi];
    const float* psih = (const float*)d_in[pi];
    float* out = (float*)d_out;

    // Output guard under the float32-elements hypothesis (64 MB buffer).
    unsigned o_lim = (unsigned)out_size;
    if (o_lim > (unsigned)OUT_ELEMS) o_lim = (unsigned)OUT_ELEMS;

    if (!quiet) {
        // Safe probes: all indices < 16777216 floats (64 MB), < input extents.
        probe_read_buf<<<1, 32>>>(x, 0u, (unsigned)(NB * SIGL - 1), 0);
        probe_read_buf<<<1, 32>>>(psih, 0u, (unsigned)(NA * UP - 1), 1);
        probe_write_out<<<1, 32>>>(out, 0u, o_lim - 1u);
        cudaError_t e = cudaStreamSynchronize(0);
        fprintf(stderr, "[DIAG] safe probes (out float idx %u): %s\n",
                o_lim - 1u, cudaGetErrorString(e));
        fflush(stderr);
    }

    cwt_fwd_kernel<<<NB, THREADS>>>(x);
    cwt_main_kernel<<<dim3(NA, NB), THREADS>>>(psih, out, o_lim);

    if (!quiet) {
        cudaError_t e = cudaStreamSynchronize(0);
        fprintf(stderr, "[DIAG] compute kernels: %s\n", cudaGetErrorString(e));
        fflush(stderr);
    }
}

// round 14
// speedup vs baseline: 4.3465x; 4.3465x over previous
#include <cuda_runtime.h>

#define UP      4096
#define HALF    2048
#define QUART   1024
#define LOG2UP  12
#define NB      32
#define NA      256
#define SIGL    2048
#define N1      1024
#define THREADS 256
#define OUT_ELEMS (NB * NA * SIGL)
#define IDX(i) ((i) + ((i) >> 3))          // smem pad: <=2-way conflicts all stages

// Forward-FFT results: (32, 4096) complex64, natural order. 1 MB static scratch.
__device__ float2 g_xh[NB * UP];

__device__ __forceinline__ float2 cmul(float2 a, float2 b) {
    return make_float2(a.x * b.x - a.y * b.y, a.x * b.y + a.y * b.x);
}
__device__ __forceinline__ float2 cadd(float2 a, float2 b) { return make_float2(a.x + b.x, a.y + b.y); }
__device__ __forceinline__ float2 csub(float2 a, float2 b) { return make_float2(a.x - b.x, a.y - b.y); }
__device__ __forceinline__ float2 muli(float2 a)  { return make_float2(-a.y, a.x); }   // *(+i)

// twq[k] = e^{+2*pi*i*k/4096}, k in [0,1024)
__device__ __forceinline__ void fill_twiddles(float2* twq) {
    for (int k = threadIdx.x; k < QUART; k += THREADS) {
        float s, c;
        sincospif((float)k * (1.0f / HALF), &s, &c);
        twq[k] = make_float2(c, s);
    }
}
// W(m) = e^{+2*pi*i*m/4096}, m in [0,4096)
__device__ __forceinline__ float2 Wm(const float2* twq, int m) {
    float2 t = twq[m & (QUART - 1)];
    if (m & QUART) t = muli(t);
    if (m & HALF)  t = make_float2(-t.x, -t.y);
    return t;
}

// ---------- verified radix-2 FFT (fwd kernel only) ----------
template <bool INVERSE>
__device__ void fft_shared_r2(float2* buf, const float2* twq) {
    const int tid = threadIdx.x;
    for (int i = tid; i < UP; i += THREADS) {
        int j = (int)(__brev((unsigned)i) >> (32 - LOG2UP));
        if (j > i) { float2 t = buf[i]; buf[i] = buf[j]; buf[j] = t; }
    }
    __syncthreads();
    for (int len = 2; len <= UP; len <<= 1) {
        const int half = len >> 1;
        const int step = UP / len;
        for (int t = tid; t < HALF; t += THREADS) {
            const int j = t & (half - 1);
            const int i = ((t & ~(half - 1)) << 1) | j;
            const int m = j * step;
            const float2 q = twq[m & (QUART - 1)];
            float2 w = (m & QUART) ? muli(q) : q;
            if (!INVERSE) w.y = -w.y;
            const float2 u = buf[i];
            const float2 v = cmul(buf[i + half], w);
            buf[i]        = cadd(u, v);
            buf[i + half] = csub(u, v);
        }
        __syncthreads();
    }
}

// Kernel 1 (verified): reflect-pad signal b, forward FFT, natural-order g_xh[b].
__global__ void cwt_fwd_kernel(const float* __restrict__ x) {
    __shared__ float2 buf[UP];
    __shared__ float2 twq[QUART];
    const int b   = blockIdx.x;
    const int tid = threadIdx.x;
    const unsigned xbase = (unsigned)b * SIGL;

    for (int i = tid; i < UP; i += THREADS) {
        int src;
        if (i < N1)             src = N1 - i;
        else if (i < N1 + SIGL) src = i - N1;
        else                    src = 5118 - i;
        buf[i] = make_float2(x[xbase + (unsigned)src], 0.0f);
    }
    fill_twiddles(twq);
    __syncthreads();

    fft_shared_r2<false>(buf, twq);

    float2* dst = g_xh + (size_t)b * UP;
    for (int i = tid; i < UP; i += THREADS) dst[i] = buf[i];
}

// 8-point DFT, inverse convention A_q = sum_r a_r e^{+2pi i qr/8}. Natural in/out.
#define C707 0.70710678118654752440f
__device__ __forceinline__ void dft8_inv(float2* a) {
    float2 b0 = cadd(a[0], a[4]), b1 = csub(a[0], a[4]);
    float2 b2 = cadd(a[2], a[6]), b3 = csub(a[2], a[6]);
    float2 b4 = cadd(a[1], a[5]), b5 = csub(a[1], a[5]);
    float2 b6 = cadd(a[3], a[7]), b7 = csub(a[3], a[7]);
    float2 t;
    float2 c0 = cadd(b0, b2), c2 = csub(b0, b2);
    t = muli(b3);
    float2 c1 = cadd(b1, t),  c3 = csub(b1, t);
    float2 c4 = cadd(b4, b6), c6 = csub(b4, b6);
    t = muli(b7);
    float2 c5 = cadd(b5, t),  c7 = csub(b5, t);
    a[0] = cadd(c0, c4); a[4] = csub(c0, c4);
    t = make_float2(C707 * (c5.x - c5.y), C707 * (c5.x + c5.y));   // *W8^1 = c(1+i)
    a[1] = cadd(c1, t);  a[5] = csub(c1, t);
    t = muli(c6);                                                   // *W8^2 = i
    a[2] = cadd(c2, t);  a[6] = csub(c2, t);
    t = make_float2(-C707 * (c7.x + c7.y), C707 * (c7.x - c7.y));   // *W8^3 = c(-1+i)
    a[3] = cadd(c3, t);  a[7] = csub(c3, t);
}

// Kernel 2: block (ap, b) handles scales a0=2ap, a1=2ap+1 via Hermitian packing.
// Z[k] = X[k]*(Pa+iPb)[k], Z[4096-k] = conj(X[k])*(Pa+iPb)[k], k in [1,2047].
// One radix-8 inverse FFT: Re -> row a0, Im -> row a1. Scale 1/8192 (1/2 * 1/4096).
__global__ void cwt_main_kernel(const float* __restrict__ psih,
                                float* __restrict__ out, unsigned o_lim) {
    __shared__ float2 buf[UP + (UP >> 3)];   // 4608 f2, padded via IDX
    __shared__ float2 twq[QUART];

    const int ap  = blockIdx.x;              // scale pair 0..127
    const int b   = blockIdx.y;              // batch 0..31
    const int tid = threadIdx.x;
    const int a0  = 2 * ap;

    fill_twiddles(twq);

    // ---- spectrum assembly (natural order) ----
    const float*  Pa = psih + (size_t)a0 * UP;
    const float*  Pb = Pa + UP;
    const float2* X  = g_xh + (size_t)b * UP;
    if (tid == 0) { buf[IDX(0)] = make_float2(0.f, 0.f); buf[IDX(HALF)] = make_float2(0.f, 0.f); }
    for (int k = 1 + tid; k < HALF; k += THREADS) {
        const float2 xv = X[k];
        const float2 C  = make_float2(Pa[k], Pb[k]);
        buf[IDX(k)]      = cmul(xv, C);
        buf[IDX(UP - k)] = cmul(make_float2(xv.x, -xv.y), C);
    }
    __syncthreads();

    // ---- octal digit-reversal permutation (involution; pair swapped once) ----
    for (int i = tid; i < UP; i += THREADS) {
        const int j = ((i & 7) << 9) | (((i >> 3) & 7) << 6) | (((i >> 6) & 7) << 3) | ((i >> 9) & 7);
        if (j > i) { float2 t = buf[IDX(i)]; buf[IDX(i)] = buf[IDX(j)]; buf[IDX(j)] = t; }
    }
    __syncthreads();

    // ---- 4 radix-8 DIT inverse stages ----
#pragma unroll
    for (int t3 = 0; t3 < 12; t3 += 3) {     // t3 = 3*stage; M = 8^stage
        const int M    = 1 << t3;
        const int step = 512 >> t3;          // 4096/(8M)
#pragma unroll
        for (int h = 0; h < 2; h++) {
            const int u    = tid + h * THREADS;       // butterfly id 0..511
            const int j    = u & (M - 1);
            const int g    = u >> t3;
            const int base = (g << (t3 + 3)) + j;     // g*8M + j
            float2 r[8];
#pragma unroll
            for (int q = 0; q < 8; q++) r[q] = buf[IDX(base + q * M)];
            if (t3 > 0) {
#pragma unroll
                for (int q = 1; q < 8; q++) r[q] = cmul(r[q], Wm(twq, j * q * step));
            }
            dft8_inv(r);
#pragma unroll
            for (int q = 0; q < 8; q++) buf[IDX(base + q * M)] = r[q];
        }
        __syncthreads();
    }

    // ---- crop + write two real rows ----
    const float inv = 1.0f / 8192.0f;        // 1/2 (Hermitian) * 1/4096 (ifft)
    const unsigned ob0 = ((unsigned)b * NA + (unsigned)a0) * SIGL;
    const unsigned ob1 = ob0 + SIGL;
    for (int n = tid; n < SIGL; n += THREADS) {
        const float2 z = buf[IDX(N1 + n)];
        const unsigned o0 = ob0 + (unsigned)n;
        const unsigned o1 = ob1 + (unsigned)n;
        if (o0 < o_lim) out[o0] = z.x * inv;
        if (o1 < o_lim) out[o1] = z.y * inv;
    }
}

extern "C" void kernel_launch(void* const* d_in, const int* in_sizes, int n_in,
                              void* d_out, int out_size) {
    // Confirmed contract (R9 diag): in[0]=x (65536 elems), in[1]=Psih (1048576),
    // out = 16777216 float32 (real part). Keep order-robust dispatch anyway.
    int xi = 0, pi = 1;
    if (n_in >= 2 && in_sizes[0] >= in_sizes[1]) { pi = 0; xi = 1; }
    const float* x    = (const float*)d_in[xi];
    const float* psih = (const float*)d_in[pi];
    float* out = (float*)d_out;

    unsigned o_lim = (unsigned)out_size;
    if (o_lim > (unsigned)OUT_ELEMS) o_lim = (unsigned)OUT_ELEMS;

    cwt_fwd_kernel<<<NB, THREADS>>>(x);
    cwt_main_kernel<<<dim3(NA / 2, NB), THREADS>>>(psih, out, o_lim);
}